// round 3
// baseline (speedup 1.0000x reference)
#include <cuda_runtime.h>
#include <cstdint>
#include <math.h>

// Problem dims
#define T_STEPS 256
#define B_SZ    32
#define C_SZ    1536
#define M_SZ    1536

#define N_ELEM_CORE (T_STEPS * B_SZ * C_SZ)   // 12,582,912

// ---------------- device scratch (static globals: no allocations) -------------
__device__ float g_u[C_SZ];
__device__ float g_v[C_SZ];
__device__ float g_t[C_SZ];
__device__ float g_scale;
__device__ float g_Ws[C_SZ * C_SZ];           // scaled W_h
__device__ float g_pre[N_ELEM_CORE];          // x_core @ W_x^T + b_core
__device__ float g_h[2][B_SZ * C_SZ];         // ping-pong hidden state

// ---------------- threefry2x32 (exact JAX PRNG core) ---------------------------
__device__ __forceinline__ uint32_t rotl32(uint32_t x, int r) {
    return (x << r) | (x >> (32 - r));
}

__device__ __forceinline__ void threefry2x32(uint32_t& x0, uint32_t& x1) {
    const uint32_t k0 = 0u, k1 = 42u;
    const uint32_t k2 = k0 ^ k1 ^ 0x1BD11BDAu;
    const uint32_t ks[3] = {k0, k1, k2};
    const int R0[4] = {13, 15, 26, 6};
    const int R1[4] = {17, 29, 16, 24};
    x0 += ks[0];
    x1 += ks[1];
#pragma unroll
    for (int i = 0; i < 5; i++) {
        const int* r = (i & 1) ? R1 : R0;
#pragma unroll
        for (int j = 0; j < 4; j++) {
            x0 += x1;
            x1 = rotl32(x1, r[j]);
            x1 ^= x0;
        }
        x0 += ks[(i + 1) % 3];
        x1 += ks[(i + 2) % 3] + (uint32_t)(i + 1);
    }
}

// bits -> standard normal exactly like jax.random.normal (fp32)
__device__ __forceinline__ float bits_to_normal(uint32_t bits) {
    float f = __uint_as_float((bits >> 9) | 0x3f800000u) - 1.0f;  // [0,1)
    const float lo = __uint_as_float(0xBF7FFFFFu);                // nextafter(-1,0)
    float val = __fadd_rn(__fmul_rn(f, 2.0f), lo);
    val = fmaxf(lo, val);
    return 1.41421354f * erfinvf(val);   // sqrt(2) in fp32
}

// ---------------- spectral-norm kernels ----------------------------------------
// Partitionable threefry (JAX >= 0.5 default): per-element 64-bit counter i,
// block = threefry2x32(key, (i>>32, i&0xffffffff)); 32-bit bits = lane0 ^ lane1.
// 512 threads, 1 block: generate u, normalize by division (no eps, matching jax)
__global__ void k_gen_u() {
    __shared__ float red[512];
    const int tid = threadIdx.x;
    float s = 0.f;
    for (int i = tid; i < C_SZ; i += 512) {
        uint32_t x0 = 0u;                 // hi 32 bits of counter (i < 2^32)
        uint32_t x1 = (uint32_t)i;        // lo 32 bits
        threefry2x32(x0, x1);
        uint32_t bits = x0 ^ x1;          // 32-bit lane combine
        float n = bits_to_normal(bits);
        g_u[i] = n;
        s += n * n;
    }
    red[tid] = s;
    __syncthreads();
    for (int o = 256; o > 0; o >>= 1) {
        if (tid < o) red[tid] += red[tid + o];
        __syncthreads();
    }
    float nrm = sqrtf(red[0]);
    for (int i = tid; i < C_SZ; i += 512) g_u[i] = g_u[i] / nrm;
}

// out = W^T u  (pure fp32)
// dst==0 -> g_v, dst==1 -> g_t (used for sigma's u@W)
__global__ void k_mv_tn(const float* __restrict__ W, int dst) {
    const int j0 = blockIdx.x * 16;
    const int c = threadIdx.x & 15;
    const int r = threadIdx.x >> 4;  // 0..15
    float acc = 0.f;
    for (int i = r; i < C_SZ; i += 16)
        acc = fmaf(W[(size_t)i * C_SZ + j0 + c], g_u[i], acc);
    __shared__ float s[16][17];
    s[r][c] = acc;
    __syncthreads();
    if (r == 0) {
        float t = 0.f;
#pragma unroll
        for (int q = 0; q < 16; q++) t += s[q][c];
        if (dst == 0) g_v[j0 + c] = t;
        else          g_t[j0 + c] = t;
    }
}

// g_t = W v : warp per row; 48 blocks x 1024 threads (pure fp32)
__global__ void k_mv_nt(const float* __restrict__ W) {
    const int row = blockIdx.x * 32 + (threadIdx.x >> 5);
    const int lane = threadIdx.x & 31;
    float acc = 0.f;
    for (int j = lane; j < C_SZ; j += 32)
        acc = fmaf(W[(size_t)row * C_SZ + j], g_v[j], acc);
#pragma unroll
    for (int o = 16; o > 0; o >>= 1) acc += __shfl_down_sync(0xffffffffu, acc, o);
    if (lane == 0) g_t[row] = acc;
}

// v /= (||v|| + eps)
__global__ void k_norm_v() {
    __shared__ float red[512];
    const int tid = threadIdx.x;
    float s = 0.f;
    for (int i = tid; i < C_SZ; i += 512) { float x = g_v[i]; s += x * x; }
    red[tid] = s;
    __syncthreads();
    for (int o = 256; o > 0; o >>= 1) {
        if (tid < o) red[tid] += red[tid + o];
        __syncthreads();
    }
    float den = sqrtf(red[0]) + 1e-8f;
    for (int i = tid; i < C_SZ; i += 512) g_v[i] = g_v[i] / den;
}

// u = t / (||t|| + eps)
__global__ void k_norm_u() {
    __shared__ float red[512];
    const int tid = threadIdx.x;
    float s = 0.f;
    for (int i = tid; i < C_SZ; i += 512) { float x = g_t[i]; s += x * x; }
    red[tid] = s;
    __syncthreads();
    for (int o = 256; o > 0; o >>= 1) {
        if (tid < o) red[tid] += red[tid + o];
        __syncthreads();
    }
    float den = sqrtf(red[0]) + 1e-8f;
    for (int i = tid; i < C_SZ; i += 512) g_u[i] = g_t[i] / den;
}

// sigma = |dot(g_t, g_v)| fp32 ; scale = 0.99/(sigma+eps)
__global__ void k_sigma() {
    __shared__ float red[512];
    const int tid = threadIdx.x;
    float s = 0.f;
    for (int i = tid; i < C_SZ; i += 512) s = fmaf(g_t[i], g_v[i], s);
    red[tid] = s;
    __syncthreads();
    for (int o = 256; o > 0; o >>= 1) {
        if (tid < o) red[tid] += red[tid + o];
        __syncthreads();
    }
    if (tid == 0) {
        float sigma = fabsf(red[0]);
        g_scale = 0.99f / (sigma + 1e-8f);
    }
}

// Ws = W_h * scale
__global__ void k_scaleW(const float* __restrict__ W) {
    const float sc = g_scale;
    size_t i = (size_t)blockIdx.x * blockDim.x + threadIdx.x;
    if (i < (size_t)C_SZ * C_SZ) g_Ws[i] = W[i] * sc;
}

// h[0] = h0_core
__global__ void k_init_h(const float* __restrict__ h0) {
    int i = blockIdx.x * blockDim.x + threadIdx.x;
    if (i < B_SZ * C_SZ) g_h[0][i] = h0[i];
}

// ---------------- phase-1 GEMM: pre = X @ Wx^T + b (pure fp32) -----------------
// 64x64 block tile, 4x4 per thread, K-chunk 16; grid (24, 128), 256 threads
__global__ void k_gemm_pre(const float* __restrict__ X,
                           const float* __restrict__ Wx,
                           const float* __restrict__ bc) {
    __shared__ float As[16][68];
    __shared__ float Bs[16][68];
    const int bm = blockIdx.y * 64;
    const int bn = blockIdx.x * 64;
    const int tid = threadIdx.x;
    const int tx = tid & 15;       // column group
    const int ty = tid >> 4;       // row group
    const int lr = tid >> 2;       // 0..63 load row
    const int lk = (tid & 3) * 4;  // 0,4,8,12 load k

    float acc[4][4] = {};

    for (int k0 = 0; k0 < C_SZ; k0 += 16) {
        float4 av = *(const float4*)&X[(size_t)(bm + lr) * C_SZ + k0 + lk];
        float4 bv = *(const float4*)&Wx[(size_t)(bn + lr) * C_SZ + k0 + lk];
        As[lk + 0][lr] = av.x; As[lk + 1][lr] = av.y;
        As[lk + 2][lr] = av.z; As[lk + 3][lr] = av.w;
        Bs[lk + 0][lr] = bv.x; Bs[lk + 1][lr] = bv.y;
        Bs[lk + 2][lr] = bv.z; Bs[lk + 3][lr] = bv.w;
        __syncthreads();
#pragma unroll
        for (int k = 0; k < 16; k++) {
            float a[4], b[4];
#pragma unroll
            for (int i = 0; i < 4; i++) a[i] = As[k][ty * 4 + i];
#pragma unroll
            for (int j = 0; j < 4; j++) b[j] = Bs[k][tx * 4 + j];
#pragma unroll
            for (int i = 0; i < 4; i++)
#pragma unroll
                for (int j = 0; j < 4; j++) acc[i][j] = fmaf(a[i], b[j], acc[i][j]);
        }
        __syncthreads();
    }

    float bb0 = bc[bn + tx * 4 + 0];
    float bb1 = bc[bn + tx * 4 + 1];
    float bb2 = bc[bn + tx * 4 + 2];
    float bb3 = bc[bn + tx * 4 + 3];
#pragma unroll
    for (int i = 0; i < 4; i++) {
        size_t row = (size_t)(bm + ty * 4 + i);
        float4 o;
        o.x = acc[i][0] + bb0; o.y = acc[i][1] + bb1;
        o.z = acc[i][2] + bb2; o.w = acc[i][3] + bb3;
        *(float4*)&g_pre[row * C_SZ + bn + tx * 4] = o;
    }
}

// ---------------- per-step recurrence kernel -----------------------------------
// h_new = tanh(pre[t] + h_old @ Ws^T); out_core[t] = h_new * silu(z_core[t])
// grid 96 blocks (16 columns each) x 128 threads, 4 outputs/thread (2b x 2c)
__global__ void k_step(const float* __restrict__ zc,
                       float* __restrict__ out_core,
                       float* __restrict__ h_core_f,
                       int t, int last) {
    const int c0 = blockIdx.x * 16;
    __shared__ float hs[32][65];
    __shared__ float ws[16][65];
    const int tid = threadIdx.x;         // 0..127
    const int cc = (tid & 7) * 2;        // local column pair base (0..14)
    const int bb = tid >> 3;             // 0..15 -> batches bb and bb+16
    const float* __restrict__ hold = g_h[t & 1];
    float* __restrict__ hnew = g_h[(t + 1) & 1];

    float a00 = 0.f, a01 = 0.f, a10 = 0.f, a11 = 0.f;

    for (int k0 = 0; k0 < C_SZ; k0 += 64) {
        float4 hv[4];
#pragma unroll
        for (int i = 0; i < 4; i++) {
            int idx = tid + i * 128;            // 0..511
            int r = idx >> 4;                   // 0..31
            int kq = (idx & 15) * 4;            // 0..60
            hv[i] = *(const float4*)&hold[r * C_SZ + k0 + kq];
        }
        float4 wv[2];
#pragma unroll
        for (int i = 0; i < 2; i++) {
            int idx = tid + i * 128;            // 0..255
            int r = idx >> 4;                   // 0..15
            int kq = (idx & 15) * 4;
            wv[i] = *(const float4*)&g_Ws[(size_t)(c0 + r) * C_SZ + k0 + kq];
        }
        __syncthreads();   // previous iteration's smem reads done
#pragma unroll
        for (int i = 0; i < 4; i++) {
            int idx = tid + i * 128;
            int r = idx >> 4;
            int kq = (idx & 15) * 4;
            hs[r][kq + 0] = hv[i].x; hs[r][kq + 1] = hv[i].y;
            hs[r][kq + 2] = hv[i].z; hs[r][kq + 3] = hv[i].w;
        }
#pragma unroll
        for (int i = 0; i < 2; i++) {
            int idx = tid + i * 128;
            int r = idx >> 4;
            int kq = (idx & 15) * 4;
            ws[r][kq + 0] = wv[i].x; ws[r][kq + 1] = wv[i].y;
            ws[r][kq + 2] = wv[i].z; ws[r][kq + 3] = wv[i].w;
        }
        __syncthreads();
#pragma unroll
        for (int k = 0; k < 64; k++) {
            float w0 = ws[cc][k], w1 = ws[cc + 1][k];
            float h0 = hs[bb][k], h1 = hs[bb + 16][k];
            a00 = fmaf(h0, w0, a00); a01 = fmaf(h0, w1, a01);
            a10 = fmaf(h1, w0, a10); a11 = fmaf(h1, w1, a11);
        }
    }

    const size_t base = (size_t)t * B_SZ * C_SZ;
    float accs[2][2] = {{a00, a01}, {a10, a11}};
#pragma unroll
    for (int i = 0; i < 2; i++) {
        int b = bb + i * 16;
#pragma unroll
        for (int j = 0; j < 2; j++) {
            int c = c0 + cc + j;
            size_t idx = base + (size_t)b * C_SZ + c;
            float h = tanhf(g_pre[idx] + accs[i][j]);
            hnew[b * C_SZ + c] = h;
            float z = zc[idx];
            out_core[idx] = h * (z * (1.0f / (1.0f + expf(-z))));
            if (last) h_core_f[b * C_SZ + c] = h;
        }
    }
}

// ---------------- memory branch (independent scan) ------------------------------
__global__ void k_mem(const float* __restrict__ xm, const float* __restrict__ zm,
                      const float* __restrict__ h0, const float* __restrict__ am,
                      float* __restrict__ out_mem, float* __restrict__ h_mem_f) {
    const int gid = blockIdx.x * blockDim.x + threadIdx.x;  // 0..49151
    const int m = gid & (M_SZ - 1);
    const float a = am[m];
    const float decay = 1.0f / (1.0f + expf(-a));
    float h = h0[gid];
    const size_t stride = (size_t)B_SZ * M_SZ;
    size_t off = gid;
    float x = xm[off], z = zm[off];
#pragma unroll 4
    for (int t = 0; t < T_STEPS; t++) {
        float xn = 0.f, zn = 0.f;
        if (t < T_STEPS - 1) { xn = xm[off + stride]; zn = zm[off + stride]; }
        h = fmaf(decay, h, x);                       // decay*h + x
        out_mem[off] = h * (z * (1.0f / (1.0f + expf(-z))));
        x = xn; z = zn; off += stride;
    }
    h_mem_f[gid] = h;
}

// ---------------- launch --------------------------------------------------------
extern "C" void kernel_launch(void* const* d_in, const int* in_sizes, int n_in,
                              void* d_out, int out_size) {
    const float* x_core  = (const float*)d_in[0];
    const float* z_core  = (const float*)d_in[1];
    const float* x_mem   = (const float*)d_in[2];
    const float* z_mem   = (const float*)d_in[3];
    const float* h0_core = (const float*)d_in[4];
    const float* h0_mem  = (const float*)d_in[5];
    const float* W_x     = (const float*)d_in[6];
    const float* W_h     = (const float*)d_in[7];
    const float* b_core  = (const float*)d_in[8];
    const float* a_mem   = (const float*)d_in[9];

    float* out       = (float*)d_out;
    float* out_core  = out;
    float* out_mem   = out + (size_t)T_STEPS * B_SZ * C_SZ;
    float* h_core_f  = out_mem + (size_t)T_STEPS * B_SZ * M_SZ;
    float* h_mem_f   = h_core_f + (size_t)B_SZ * C_SZ;

    // spectral norm of W_h -> g_scale
    k_gen_u<<<1, 512>>>();
    for (int it = 0; it < 3; it++) {
        k_mv_tn<<<96, 256>>>(W_h, 0);
        k_norm_v<<<1, 512>>>();
        k_mv_nt<<<48, 1024>>>(W_h);
        k_norm_u<<<1, 512>>>();
    }
    k_mv_tn<<<96, 256>>>(W_h, 1);   // g_t = W^T u_final  (= u @ W)
    k_sigma<<<1, 512>>>();          // sigma = dot(g_t, g_v); scale
    k_scaleW<<<2304, 1024>>>(W_h);
    k_init_h<<<96, 512>>>(h0_core);

    // pre = x_core @ W_x^T + b_core
    {
        dim3 grid(C_SZ / 64, (T_STEPS * B_SZ) / 64);  // (24, 128)
        k_gemm_pre<<<grid, 256>>>(x_core, W_x, b_core);
    }

    // memory branch (independent)
    k_mem<<<192, 256>>>(x_mem, z_mem, h0_mem, a_mem, out_mem, h_mem_f);

    // sequential core recurrence
    for (int t = 0; t < T_STEPS; t++)
        k_step<<<96, 128>>>(z_core, out_core, h_core_f, t, (t == T_STEPS - 1) ? 1 : 0);
}

// round 5
// speedup vs baseline: 3.9162x; 3.9162x over previous
#include <cuda_runtime.h>
#include <cuda_fp16.h>
#include <cstdint>
#include <math.h>

// Problem dims
#define T_STEPS 256
#define B_SZ    32
#define C_SZ    1536
#define M_SZ    1536

#define N_ELEM_CORE (T_STEPS * B_SZ * C_SZ)   // 12,582,912

// ---------------- device scratch (static globals: no allocations) -------------
__device__ float g_u[C_SZ];
__device__ float g_v[C_SZ];
__device__ float g_t[C_SZ];
__device__ float g_scale;
__device__ float g_pre[N_ELEM_CORE];                       // x@Wx^T + b
__device__ __align__(16) __half g_Ws16[C_SZ * C_SZ];       // fp16 scaled W_h
__device__ __align__(16) __half g_Wx16[C_SZ * C_SZ];       // fp16 W_x
__device__ __align__(16) __half g_X16[N_ELEM_CORE];        // fp16 x_core
__device__ __align__(16) __half g_h16[2][B_SZ * C_SZ];     // fp16 hidden ping-pong

// ---------------- threefry2x32 (exact JAX partitionable PRNG) ------------------
__device__ __forceinline__ uint32_t rotl32(uint32_t x, int r) {
    return (x << r) | (x >> (32 - r));
}

__device__ __forceinline__ void threefry2x32(uint32_t& x0, uint32_t& x1) {
    const uint32_t k0 = 0u, k1 = 42u;
    const uint32_t k2 = k0 ^ k1 ^ 0x1BD11BDAu;
    const uint32_t ks[3] = {k0, k1, k2};
    const int R0[4] = {13, 15, 26, 6};
    const int R1[4] = {17, 29, 16, 24};
    x0 += ks[0];
    x1 += ks[1];
#pragma unroll
    for (int i = 0; i < 5; i++) {
        const int* r = (i & 1) ? R1 : R0;
#pragma unroll
        for (int j = 0; j < 4; j++) {
            x0 += x1;
            x1 = rotl32(x1, r[j]);
            x1 ^= x0;
        }
        x0 += ks[(i + 1) % 3];
        x1 += ks[(i + 2) % 3] + (uint32_t)(i + 1);
    }
}

__device__ __forceinline__ float bits_to_normal(uint32_t bits) {
    float f = __uint_as_float((bits >> 9) | 0x3f800000u) - 1.0f;  // [0,1)
    const float lo = __uint_as_float(0xBF7FFFFFu);                // nextafter(-1,0)
    float val = __fadd_rn(__fmul_rn(f, 2.0f), lo);
    val = fmaxf(lo, val);
    return 1.41421354f * erfinvf(val);
}

// ---------------- spectral-norm kernels (fp32, verified exact) -----------------
__global__ void k_gen_u() {
    __shared__ float red[512];
    const int tid = threadIdx.x;
    float s = 0.f;
    for (int i = tid; i < C_SZ; i += 512) {
        uint32_t x0 = 0u;
        uint32_t x1 = (uint32_t)i;
        threefry2x32(x0, x1);
        uint32_t bits = x0 ^ x1;
        float n = bits_to_normal(bits);
        g_u[i] = n;
        s += n * n;
    }
    red[tid] = s;
    __syncthreads();
    for (int o = 256; o > 0; o >>= 1) {
        if (tid < o) red[tid] += red[tid + o];
        __syncthreads();
    }
    float nrm = sqrtf(red[0]);
    for (int i = tid; i < C_SZ; i += 512) g_u[i] = g_u[i] / nrm;
}

__global__ void k_mv_tn(const float* __restrict__ W, int dst) {
    const int j0 = blockIdx.x * 16;
    const int c = threadIdx.x & 15;
    const int r = threadIdx.x >> 4;
    float acc = 0.f;
    for (int i = r; i < C_SZ; i += 16)
        acc = fmaf(W[(size_t)i * C_SZ + j0 + c], g_u[i], acc);
    __shared__ float s[16][17];
    s[r][c] = acc;
    __syncthreads();
    if (r == 0) {
        float t = 0.f;
#pragma unroll
        for (int q = 0; q < 16; q++) t += s[q][c];
        if (dst == 0) g_v[j0 + c] = t;
        else          g_t[j0 + c] = t;
    }
}

__global__ void k_mv_nt(const float* __restrict__ W) {
    const int row = blockIdx.x * 32 + (threadIdx.x >> 5);
    const int lane = threadIdx.x & 31;
    float acc = 0.f;
    for (int j = lane; j < C_SZ; j += 32)
        acc = fmaf(W[(size_t)row * C_SZ + j], g_v[j], acc);
#pragma unroll
    for (int o = 16; o > 0; o >>= 1) acc += __shfl_down_sync(0xffffffffu, acc, o);
    if (lane == 0) g_t[row] = acc;
}

__global__ void k_norm_v() {
    __shared__ float red[512];
    const int tid = threadIdx.x;
    float s = 0.f;
    for (int i = tid; i < C_SZ; i += 512) { float x = g_v[i]; s += x * x; }
    red[tid] = s;
    __syncthreads();
    for (int o = 256; o > 0; o >>= 1) {
        if (tid < o) red[tid] += red[tid + o];
        __syncthreads();
    }
    float den = sqrtf(red[0]) + 1e-8f;
    for (int i = tid; i < C_SZ; i += 512) g_v[i] = g_v[i] / den;
}

__global__ void k_norm_u() {
    __shared__ float red[512];
    const int tid = threadIdx.x;
    float s = 0.f;
    for (int i = tid; i < C_SZ; i += 512) { float x = g_t[i]; s += x * x; }
    red[tid] = s;
    __syncthreads();
    for (int o = 256; o > 0; o >>= 1) {
        if (tid < o) red[tid] += red[tid + o];
        __syncthreads();
    }
    float den = sqrtf(red[0]) + 1e-8f;
    for (int i = tid; i < C_SZ; i += 512) g_u[i] = g_t[i] / den;
}

__global__ void k_sigma() {
    __shared__ float red[512];
    const int tid = threadIdx.x;
    float s = 0.f;
    for (int i = tid; i < C_SZ; i += 512) s = fmaf(g_t[i], g_v[i], s);
    red[tid] = s;
    __syncthreads();
    for (int o = 256; o > 0; o >>= 1) {
        if (tid < o) red[tid] += red[tid + o];
        __syncthreads();
    }
    if (tid == 0) {
        float sigma = fabsf(red[0]);
        g_scale = 0.99f / (sigma + 1e-8f);
    }
}

// Ws16 = fp16(W_h * scale)   (globals referenced in DEVICE code only)
__global__ void k_scaleW16(const float* __restrict__ W) {
    const float sc = g_scale;
    size_t i = (size_t)blockIdx.x * blockDim.x + threadIdx.x;   // half2 index
    if (i < (size_t)C_SZ * C_SZ / 2) {
        float2 v = ((const float2*)W)[i];
        ((__half2*)g_Ws16)[i] = __floats2half2_rn(v.x * sc, v.y * sc);
    }
}

// Wx16 = fp16(W_x)
__global__ void k_convWx(const float* __restrict__ W) {
    size_t i = (size_t)blockIdx.x * blockDim.x + threadIdx.x;
    if (i < (size_t)C_SZ * C_SZ / 2) {
        float2 v = ((const float2*)W)[i];
        ((__half2*)g_Wx16)[i] = __floats2half2_rn(v.x, v.y);
    }
}

// X16 = fp16(x_core)
__global__ void k_convX(const float* __restrict__ X) {
    size_t i = (size_t)blockIdx.x * blockDim.x + threadIdx.x;
    if (i < (size_t)N_ELEM_CORE / 2) {
        float2 v = ((const float2*)X)[i];
        ((__half2*)g_X16)[i] = __floats2half2_rn(v.x, v.y);
    }
}

// h16[0] = fp16(h0_core)
__global__ void k_init_h16(const float* __restrict__ h0) {
    int i = blockIdx.x * blockDim.x + threadIdx.x;
    if (i < B_SZ * C_SZ / 2) {
        float2 v = ((const float2*)h0)[i];
        ((__half2*)g_h16[0])[i] = __floats2half2_rn(v.x, v.y);
    }
}

// ---------------- mma.sync m16n8k16 fp16 -> fp32 -------------------------------
__device__ __forceinline__ void mma16816(float* d, const uint32_t* a, const uint32_t* b) {
    asm volatile(
        "mma.sync.aligned.m16n8k16.row.col.f32.f16.f16.f32 "
        "{%0,%1,%2,%3},{%4,%5,%6,%7},{%8,%9},{%0,%1,%2,%3};"
        : "+f"(d[0]), "+f"(d[1]), "+f"(d[2]), "+f"(d[3])
        : "r"(a[0]), "r"(a[1]), "r"(a[2]), "r"(a[3]), "r"(b[0]), "r"(b[1]));
}

// ---------------- phase-1 GEMM: pre = X @ Wx^T + b (fp16 TC) -------------------
// grid (24, 128), 128 threads. Block tile 64(M) x 64(N), K-chunk 64.
// Warp (wm, wn) in 2x2 computes 32x32.
__global__ void k_gemm16(const float* __restrict__ bc) {
    __shared__ __half As[64][72];
    __shared__ __half Bs[64][72];
    const int bm = blockIdx.y * 64;
    const int bn = blockIdx.x * 64;
    const int tid = threadIdx.x;
    const int w = tid >> 5;
    const int lane = tid & 31;
    const int wm = w >> 1, wn = w & 1;
    const int g = lane >> 2, tg = lane & 3;

    const __half* X = g_X16;
    const __half* Wx = g_Wx16;

    float acc[2][4][4];
#pragma unroll
    for (int i = 0; i < 2; i++)
#pragma unroll
        for (int j = 0; j < 4; j++)
#pragma unroll
            for (int q = 0; q < 4; q++) acc[i][j][q] = 0.f;

    for (int k0 = 0; k0 < C_SZ; k0 += 64) {
#pragma unroll
        for (int it = 0; it < 4; it++) {
            int i = tid + it * 128;       // 0..511
            int r = i >> 3;               // 0..63
            int c = (i & 7) * 8;          // 0..56
            *(float4*)&As[r][c] = *(const float4*)&X[(size_t)(bm + r) * C_SZ + k0 + c];
            *(float4*)&Bs[r][c] = *(const float4*)&Wx[(size_t)(bn + r) * C_SZ + k0 + c];
        }
        __syncthreads();
#pragma unroll
        for (int kt = 0; kt < 4; kt++) {
            int k = kt * 16;
            uint32_t a[2][4], b[4][2];
#pragma unroll
            for (int mi = 0; mi < 2; mi++) {
                int r0 = wm * 32 + mi * 16 + g;
                a[mi][0] = *(const uint32_t*)&As[r0][k + 2 * tg];
                a[mi][1] = *(const uint32_t*)&As[r0 + 8][k + 2 * tg];
                a[mi][2] = *(const uint32_t*)&As[r0][k + 2 * tg + 8];
                a[mi][3] = *(const uint32_t*)&As[r0 + 8][k + 2 * tg + 8];
            }
#pragma unroll
            for (int ni = 0; ni < 4; ni++) {
                int r0 = wn * 32 + ni * 8 + g;
                b[ni][0] = *(const uint32_t*)&Bs[r0][k + 2 * tg];
                b[ni][1] = *(const uint32_t*)&Bs[r0][k + 2 * tg + 8];
            }
#pragma unroll
            for (int mi = 0; mi < 2; mi++)
#pragma unroll
                for (int ni = 0; ni < 4; ni++)
                    mma16816(acc[mi][ni], a[mi], b[ni]);
        }
        __syncthreads();
    }

#pragma unroll
    for (int mi = 0; mi < 2; mi++) {
        int row = bm + wm * 32 + mi * 16 + g;
#pragma unroll
        for (int ni = 0; ni < 4; ni++) {
            int col = bn + wn * 32 + ni * 8 + 2 * tg;
            float b0 = bc[col], b1 = bc[col + 1];
            float2 o0 = make_float2(acc[mi][ni][0] + b0, acc[mi][ni][1] + b1);
            float2 o1 = make_float2(acc[mi][ni][2] + b0, acc[mi][ni][3] + b1);
            *(float2*)&g_pre[(size_t)row * C_SZ + col] = o0;
            *(float2*)&g_pre[(size_t)(row + 8) * C_SZ + col] = o1;
        }
    }
}

// ---------------- per-step recurrence kernel (fp16 TC) -------------------------
// 96 blocks x 256 threads. Block owns 16 output cols. 8 warps split K (192 each).
#define SH 1544   // padded half stride
#define SMEM_STEP ((48 * SH) * 2 + 8 * 512 * 4)   // h(32) + W(16) halves + red

__global__ void k_step16(const float* __restrict__ zc,
                         float* __restrict__ out_core,
                         float* __restrict__ h_core_f,
                         int t, int last) {
    extern __shared__ __align__(16) char smem[];
    __half* hsm = (__half*)smem;                    // [32][SH]
    __half* wsm = hsm + 32 * SH;                    // [16][SH]
    float* red = (float*)(smem + (size_t)48 * SH * 2);  // [8][512]

    const int n0 = blockIdx.x * 16;
    const int tid = threadIdx.x;
    const int w = tid >> 5;
    const int lane = tid & 31;
    const int g = lane >> 2, tg = lane & 3;

    const __half* hprev = g_h16[t & 1];
    __half* hnext = g_h16[(t + 1) & 1];

    // stage h (6144 float4) and W slice (3072 float4)
#pragma unroll
    for (int it = 0; it < 24; it++) {
        int i = tid + it * 256;
        int r = i / 192, c = (i % 192) * 8;
        *(float4*)&hsm[r * SH + c] = ((const float4*)hprev)[i];
    }
#pragma unroll
    for (int it = 0; it < 12; it++) {
        int i = tid + it * 256;
        int r = i / 192, c = (i % 192) * 8;
        *(float4*)&wsm[r * SH + c] = *(const float4*)&g_Ws16[(size_t)(n0 + r) * C_SZ + c];
    }
    __syncthreads();

    float acc[2][2][4];
#pragma unroll
    for (int i = 0; i < 2; i++)
#pragma unroll
        for (int j = 0; j < 2; j++)
#pragma unroll
            for (int q = 0; q < 4; q++) acc[i][j][q] = 0.f;

    const int kbase = w * 192;
#pragma unroll
    for (int kt = 0; kt < 12; kt++) {
        int k0 = kbase + kt * 16;
        uint32_t a[2][4], b[2][2];
#pragma unroll
        for (int mi = 0; mi < 2; mi++) {
            int r0 = mi * 16 + g;
            a[mi][0] = *(const uint32_t*)&hsm[r0 * SH + k0 + 2 * tg];
            a[mi][1] = *(const uint32_t*)&hsm[(r0 + 8) * SH + k0 + 2 * tg];
            a[mi][2] = *(const uint32_t*)&hsm[r0 * SH + k0 + 2 * tg + 8];
            a[mi][3] = *(const uint32_t*)&hsm[(r0 + 8) * SH + k0 + 2 * tg + 8];
        }
#pragma unroll
        for (int ni = 0; ni < 2; ni++) {
            int r0 = ni * 8 + g;
            b[ni][0] = *(const uint32_t*)&wsm[r0 * SH + k0 + 2 * tg];
            b[ni][1] = *(const uint32_t*)&wsm[r0 * SH + k0 + 2 * tg + 8];
        }
#pragma unroll
        for (int mi = 0; mi < 2; mi++)
#pragma unroll
            for (int ni = 0; ni < 2; ni++)
                mma16816(acc[mi][ni], a[mi], b[ni]);
    }

    // write warp partials: out flat index = row(b)*16 + col(n local)
#pragma unroll
    for (int mi = 0; mi < 2; mi++)
#pragma unroll
        for (int ni = 0; ni < 2; ni++) {
            int r0 = mi * 16 + g;
            int c0 = ni * 8 + 2 * tg;
            *(float2*)&red[w * 512 + r0 * 16 + c0] =
                make_float2(acc[mi][ni][0], acc[mi][ni][1]);
            *(float2*)&red[w * 512 + (r0 + 8) * 16 + c0] =
                make_float2(acc[mi][ni][2], acc[mi][ni][3]);
        }
    __syncthreads();

    const size_t base = (size_t)t * B_SZ * C_SZ;
#pragma unroll
    for (int rep = 0; rep < 2; rep++) {
        int o = tid + rep * 256;
        float s = red[o];
#pragma unroll
        for (int q = 1; q < 8; q++) s += red[q * 512 + o];
        int b = o >> 4;
        int c = n0 + (o & 15);
        size_t idx = base + (size_t)b * C_SZ + c;
        float h = tanhf(g_pre[idx] + s);
        hnext[b * C_SZ + c] = __float2half_rn(h);
        float z = zc[idx];
        out_core[idx] = h * (z * (1.0f / (1.0f + expf(-z))));
        if (last) h_core_f[b * C_SZ + c] = h;
    }
}

// ---------------- memory branch (independent scan) ------------------------------
__global__ void k_mem(const float* __restrict__ xm, const float* __restrict__ zm,
                      const float* __restrict__ h0, const float* __restrict__ am,
                      float* __restrict__ out_mem, float* __restrict__ h_mem_f) {
    const int gid = blockIdx.x * blockDim.x + threadIdx.x;
    const int m = gid & (M_SZ - 1);
    const float a = am[m];
    const float decay = 1.0f / (1.0f + expf(-a));
    float h = h0[gid];
    const size_t stride = (size_t)B_SZ * M_SZ;
    size_t off = gid;
    float x = xm[off], z = zm[off];
#pragma unroll 4
    for (int t = 0; t < T_STEPS; t++) {
        float xn = 0.f, zn = 0.f;
        if (t < T_STEPS - 1) { xn = xm[off + stride]; zn = zm[off + stride]; }
        h = fmaf(decay, h, x);
        out_mem[off] = h * (z * (1.0f / (1.0f + expf(-z))));
        x = xn; z = zn; off += stride;
    }
    h_mem_f[gid] = h;
}

// ---------------- launch --------------------------------------------------------
extern "C" void kernel_launch(void* const* d_in, const int* in_sizes, int n_in,
                              void* d_out, int out_size) {
    const float* x_core  = (const float*)d_in[0];
    const float* z_core  = (const float*)d_in[1];
    const float* x_mem   = (const float*)d_in[2];
    const float* z_mem   = (const float*)d_in[3];
    const float* h0_core = (const float*)d_in[4];
    const float* h0_mem  = (const float*)d_in[5];
    const float* W_x     = (const float*)d_in[6];
    const float* W_h     = (const float*)d_in[7];
    const float* b_core  = (const float*)d_in[8];
    const float* a_mem   = (const float*)d_in[9];

    float* out       = (float*)d_out;
    float* out_core  = out;
    float* out_mem   = out + (size_t)T_STEPS * B_SZ * C_SZ;
    float* h_core_f  = out_mem + (size_t)T_STEPS * B_SZ * M_SZ;
    float* h_mem_f   = h_core_f + (size_t)B_SZ * C_SZ;

    cudaFuncSetAttribute(k_step16, cudaFuncAttributeMaxDynamicSharedMemorySize,
                         SMEM_STEP);

    // spectral norm of W_h -> g_scale
    k_gen_u<<<1, 512>>>();
    for (int it = 0; it < 3; it++) {
        k_mv_tn<<<96, 256>>>(W_h, 0);
        k_norm_v<<<1, 512>>>();
        k_mv_nt<<<48, 1024>>>(W_h);
        k_norm_u<<<1, 512>>>();
    }
    k_mv_tn<<<96, 256>>>(W_h, 1);   // g_t = u @ W
    k_sigma<<<1, 512>>>();

    // fp16 conversions (device globals referenced only in device code)
    k_scaleW16<<<(C_SZ * C_SZ / 2 + 255) / 256, 256>>>(W_h);
    k_convWx<<<(C_SZ * C_SZ / 2 + 255) / 256, 256>>>(W_x);
    k_convX<<<(N_ELEM_CORE / 2 + 255) / 256, 256>>>(x_core);
    k_init_h16<<<(B_SZ * C_SZ / 2 + 255) / 256, 256>>>(h0_core);

    // pre = x_core @ W_x^T + b_core (tensor cores)
    {
        dim3 grid(C_SZ / 64, (T_STEPS * B_SZ) / 64);  // (24, 128)
        k_gemm16<<<grid, 128>>>(b_core);
    }

    // memory branch (independent)
    k_mem<<<192, 256>>>(x_mem, z_mem, h0_mem, a_mem, out_mem, h_mem_f);

    // sequential core recurrence (tensor cores)
    for (int t = 0; t < T_STEPS; t++)
        k_step16<<<96, 256, SMEM_STEP>>>(z_core, out_core, h_core_f, t,
                                         (t == T_STEPS - 1) ? 1 : 0);
}

// round 6
// speedup vs baseline: 4.8609x; 1.2412x over previous
#include <cuda_runtime.h>
#include <cuda_fp16.h>
#include <cstdint>
#include <math.h>

// Problem dims
#define T_STEPS 256
#define B_SZ    32
#define C_SZ    1536
#define M_SZ    1536
#define NBLK    96

#define N_ELEM_CORE (T_STEPS * B_SZ * C_SZ)   // 12,582,912

// ---------------- device scratch (static globals: no allocations) -------------
__device__ float g_u[C_SZ];
__device__ float g_v[C_SZ];
__device__ float g_t[C_SZ];
__device__ float g_scale;
__device__ float g_pre[N_ELEM_CORE];                       // x@Wx^T + b
__device__ __align__(16) __half g_Ws16[C_SZ * C_SZ];       // fp16 scaled W_h
__device__ __align__(16) __half g_Wx16[C_SZ * C_SZ];       // fp16 W_x
__device__ __align__(16) __half g_X16[N_ELEM_CORE];        // fp16 x_core
__device__ __align__(16) __half g_h16[3][B_SZ * C_SZ];     // fp16 hidden, 3-deep
__device__ unsigned g_bar_ctr;                             // grid barrier counter

// ---------------- threefry2x32 (exact JAX partitionable PRNG) ------------------
__device__ __forceinline__ uint32_t rotl32(uint32_t x, int r) {
    return (x << r) | (x >> (32 - r));
}

__device__ __forceinline__ void threefry2x32(uint32_t& x0, uint32_t& x1) {
    const uint32_t k0 = 0u, k1 = 42u;
    const uint32_t k2 = k0 ^ k1 ^ 0x1BD11BDAu;
    const uint32_t ks[3] = {k0, k1, k2};
    const int R0[4] = {13, 15, 26, 6};
    const int R1[4] = {17, 29, 16, 24};
    x0 += ks[0];
    x1 += ks[1];
#pragma unroll
    for (int i = 0; i < 5; i++) {
        const int* r = (i & 1) ? R1 : R0;
#pragma unroll
        for (int j = 0; j < 4; j++) {
            x0 += x1;
            x1 = rotl32(x1, r[j]);
            x1 ^= x0;
        }
        x0 += ks[(i + 1) % 3];
        x1 += ks[(i + 2) % 3] + (uint32_t)(i + 1);
    }
}

__device__ __forceinline__ float bits_to_normal(uint32_t bits) {
    float f = __uint_as_float((bits >> 9) | 0x3f800000u) - 1.0f;  // [0,1)
    const float lo = __uint_as_float(0xBF7FFFFFu);                // nextafter(-1,0)
    float val = __fadd_rn(__fmul_rn(f, 2.0f), lo);
    val = fmaxf(lo, val);
    return 1.41421354f * erfinvf(val);
}

// ---------------- spectral-norm kernels (fp32, verified exact) -----------------
__global__ void k_gen_u() {
    __shared__ float red[512];
    const int tid = threadIdx.x;
    float s = 0.f;
    for (int i = tid; i < C_SZ; i += 512) {
        uint32_t x0 = 0u;
        uint32_t x1 = (uint32_t)i;
        threefry2x32(x0, x1);
        uint32_t bits = x0 ^ x1;
        float n = bits_to_normal(bits);
        g_u[i] = n;
        s += n * n;
    }
    red[tid] = s;
    __syncthreads();
    for (int o = 256; o > 0; o >>= 1) {
        if (tid < o) red[tid] += red[tid + o];
        __syncthreads();
    }
    float nrm = sqrtf(red[0]);
    for (int i = tid; i < C_SZ; i += 512) g_u[i] = g_u[i] / nrm;
}

__global__ void k_mv_tn(const float* __restrict__ W, int dst) {
    const int j0 = blockIdx.x * 16;
    const int c = threadIdx.x & 15;
    const int r = threadIdx.x >> 4;
    float acc = 0.f;
    for (int i = r; i < C_SZ; i += 16)
        acc = fmaf(W[(size_t)i * C_SZ + j0 + c], g_u[i], acc);
    __shared__ float s[16][17];
    s[r][c] = acc;
    __syncthreads();
    if (r == 0) {
        float t = 0.f;
#pragma unroll
        for (int q = 0; q < 16; q++) t += s[q][c];
        if (dst == 0) g_v[j0 + c] = t;
        else          g_t[j0 + c] = t;
    }
}

__global__ void k_mv_nt(const float* __restrict__ W) {
    const int row = blockIdx.x * 32 + (threadIdx.x >> 5);
    const int lane = threadIdx.x & 31;
    float acc = 0.f;
    for (int j = lane; j < C_SZ; j += 32)
        acc = fmaf(W[(size_t)row * C_SZ + j], g_v[j], acc);
#pragma unroll
    for (int o = 16; o > 0; o >>= 1) acc += __shfl_down_sync(0xffffffffu, acc, o);
    if (lane == 0) g_t[row] = acc;
}

__global__ void k_norm_v() {
    __shared__ float red[512];
    const int tid = threadIdx.x;
    float s = 0.f;
    for (int i = tid; i < C_SZ; i += 512) { float x = g_v[i]; s += x * x; }
    red[tid] = s;
    __syncthreads();
    for (int o = 256; o > 0; o >>= 1) {
        if (tid < o) red[tid] += red[tid + o];
        __syncthreads();
    }
    float den = sqrtf(red[0]) + 1e-8f;
    for (int i = tid; i < C_SZ; i += 512) g_v[i] = g_v[i] / den;
}

__global__ void k_norm_u() {
    __shared__ float red[512];
    const int tid = threadIdx.x;
    float s = 0.f;
    for (int i = tid; i < C_SZ; i += 512) { float x = g_t[i]; s += x * x; }
    red[tid] = s;
    __syncthreads();
    for (int o = 256; o > 0; o >>= 1) {
        if (tid < o) red[tid] += red[tid + o];
        __syncthreads();
    }
    float den = sqrtf(red[0]) + 1e-8f;
    for (int i = tid; i < C_SZ; i += 512) g_u[i] = g_t[i] / den;
}

__global__ void k_sigma() {
    __shared__ float red[512];
    const int tid = threadIdx.x;
    float s = 0.f;
    for (int i = tid; i < C_SZ; i += 512) s = fmaf(g_t[i], g_v[i], s);
    red[tid] = s;
    __syncthreads();
    for (int o = 256; o > 0; o >>= 1) {
        if (tid < o) red[tid] += red[tid + o];
        __syncthreads();
    }
    if (tid == 0) {
        float sigma = fabsf(red[0]);
        g_scale = 0.99f / (sigma + 1e-8f);
    }
}

// Ws16 = fp16(W_h * scale)
__global__ void k_scaleW16(const float* __restrict__ W) {
    const float sc = g_scale;
    size_t i = (size_t)blockIdx.x * blockDim.x + threadIdx.x;
    if (i < (size_t)C_SZ * C_SZ / 2) {
        float2 v = ((const float2*)W)[i];
        ((__half2*)g_Ws16)[i] = __floats2half2_rn(v.x * sc, v.y * sc);
    }
}

// Wx16 = fp16(W_x)
__global__ void k_convWx(const float* __restrict__ W) {
    size_t i = (size_t)blockIdx.x * blockDim.x + threadIdx.x;
    if (i < (size_t)C_SZ * C_SZ / 2) {
        float2 v = ((const float2*)W)[i];
        ((__half2*)g_Wx16)[i] = __floats2half2_rn(v.x, v.y);
    }
}

// X16 = fp16(x_core)
__global__ void k_convX(const float* __restrict__ X) {
    size_t i = (size_t)blockIdx.x * blockDim.x + threadIdx.x;
    if (i < (size_t)N_ELEM_CORE / 2) {
        float2 v = ((const float2*)X)[i];
        ((__half2*)g_X16)[i] = __floats2half2_rn(v.x, v.y);
    }
}

// h16[0] = fp16(h0_core); also reset grid barrier (runs before persistent kernel)
__global__ void k_init_h16(const float* __restrict__ h0) {
    int i = blockIdx.x * blockDim.x + threadIdx.x;
    if (i == 0) g_bar_ctr = 0u;
    if (i < B_SZ * C_SZ / 2) {
        float2 v = ((const float2*)h0)[i];
        ((__half2*)g_h16[0])[i] = __floats2half2_rn(v.x, v.y);
    }
}

// ---------------- mma.sync m16n8k16 fp16 -> fp32 -------------------------------
__device__ __forceinline__ void mma16816(float* d, const uint32_t* a, const uint32_t* b) {
    asm volatile(
        "mma.sync.aligned.m16n8k16.row.col.f32.f16.f16.f32 "
        "{%0,%1,%2,%3},{%4,%5,%6,%7},{%8,%9},{%0,%1,%2,%3};"
        : "+f"(d[0]), "+f"(d[1]), "+f"(d[2]), "+f"(d[3])
        : "r"(a[0]), "r"(a[1]), "r"(a[2]), "r"(a[3]), "r"(b[0]), "r"(b[1]));
}

// ---------------- phase-1 GEMM: pre = X @ Wx^T + b (fp16 TC) -------------------
__global__ void k_gemm16(const float* __restrict__ bc) {
    __shared__ __half As[64][72];
    __shared__ __half Bs[64][72];
    const int bm = blockIdx.y * 64;
    const int bn = blockIdx.x * 64;
    const int tid = threadIdx.x;
    const int w = tid >> 5;
    const int lane = tid & 31;
    const int wm = w >> 1, wn = w & 1;
    const int g = lane >> 2, tg = lane & 3;

    const __half* X = g_X16;
    const __half* Wx = g_Wx16;

    float acc[2][4][4];
#pragma unroll
    for (int i = 0; i < 2; i++)
#pragma unroll
        for (int j = 0; j < 4; j++)
#pragma unroll
            for (int q = 0; q < 4; q++) acc[i][j][q] = 0.f;

    for (int k0 = 0; k0 < C_SZ; k0 += 64) {
#pragma unroll
        for (int it = 0; it < 4; it++) {
            int i = tid + it * 128;
            int r = i >> 3;
            int c = (i & 7) * 8;
            *(float4*)&As[r][c] = *(const float4*)&X[(size_t)(bm + r) * C_SZ + k0 + c];
            *(float4*)&Bs[r][c] = *(const float4*)&Wx[(size_t)(bn + r) * C_SZ + k0 + c];
        }
        __syncthreads();
#pragma unroll
        for (int kt = 0; kt < 4; kt++) {
            int k = kt * 16;
            uint32_t a[2][4], b[4][2];
#pragma unroll
            for (int mi = 0; mi < 2; mi++) {
                int r0 = wm * 32 + mi * 16 + g;
                a[mi][0] = *(const uint32_t*)&As[r0][k + 2 * tg];
                a[mi][1] = *(const uint32_t*)&As[r0 + 8][k + 2 * tg];
                a[mi][2] = *(const uint32_t*)&As[r0][k + 2 * tg + 8];
                a[mi][3] = *(const uint32_t*)&As[r0 + 8][k + 2 * tg + 8];
            }
#pragma unroll
            for (int ni = 0; ni < 4; ni++) {
                int r0 = wn * 32 + ni * 8 + g;
                b[ni][0] = *(const uint32_t*)&Bs[r0][k + 2 * tg];
                b[ni][1] = *(const uint32_t*)&Bs[r0][k + 2 * tg + 8];
            }
#pragma unroll
            for (int mi = 0; mi < 2; mi++)
#pragma unroll
                for (int ni = 0; ni < 4; ni++)
                    mma16816(acc[mi][ni], a[mi], b[ni]);
        }
        __syncthreads();
    }

#pragma unroll
    for (int mi = 0; mi < 2; mi++) {
        int row = bm + wm * 32 + mi * 16 + g;
#pragma unroll
        for (int ni = 0; ni < 4; ni++) {
            int col = bn + wn * 32 + ni * 8 + 2 * tg;
            float b0 = bc[col], b1 = bc[col + 1];
            float2 o0 = make_float2(acc[mi][ni][0] + b0, acc[mi][ni][1] + b1);
            float2 o1 = make_float2(acc[mi][ni][2] + b0, acc[mi][ni][3] + b1);
            *(float2*)&g_pre[(size_t)row * C_SZ + col] = o0;
            *(float2*)&g_pre[(size_t)(row + 8) * C_SZ + col] = o1;
        }
    }
}

// ---------------- persistent recurrence kernel (fp16 TC, grid barrier) ---------
// 96 blocks x 256 threads, 1 block/SM. Block owns 16 output cols for all steps.
// W slice stays resident in smem. h cycles through 3 global fp16 buffers.
#define SH 1544   // padded half stride
#define SMEM_STEP ((48 * SH) * 2 + 8 * 512 * 4)   // h(32) + W(16) halves + red

__global__ void __launch_bounds__(256, 1)
k_recurrent(const float* __restrict__ zc,
            float* __restrict__ out_core,
            float* __restrict__ h_core_f) {
    extern __shared__ __align__(16) char smem[];
    __half* hsm = (__half*)smem;                         // [32][SH]
    __half* wsm = hsm + 32 * SH;                         // [16][SH]
    float* red = (float*)(smem + (size_t)48 * SH * 2);   // [8][512]

    const int n0 = blockIdx.x * 16;
    const int tid = threadIdx.x;
    const int w = tid >> 5;
    const int lane = tid & 31;
    const int g = lane >> 2, tg = lane & 3;

    // stage W slice ONCE (16 rows x 1536 halves)
#pragma unroll
    for (int it = 0; it < 12; it++) {
        int i = tid + it * 256;
        int r = i / 192, c = (i % 192) * 8;
        *(float4*)&wsm[r * SH + c] = *(const float4*)&g_Ws16[(size_t)(n0 + r) * C_SZ + c];
    }

    for (int t = 0; t < T_STEPS; t++) {
        const __half* hprev = g_h16[t % 3];
        __half* hnext = g_h16[(t + 1) % 3];

        // stage h (6144 float4)
#pragma unroll
        for (int it = 0; it < 24; it++) {
            int i = tid + it * 256;
            int r = i / 192, c = (i % 192) * 8;
            *(float4*)&hsm[r * SH + c] = ((const float4*)hprev)[i];
        }
        __syncthreads();

        float acc[2][2][4];
#pragma unroll
        for (int i = 0; i < 2; i++)
#pragma unroll
            for (int j = 0; j < 2; j++)
#pragma unroll
                for (int q = 0; q < 4; q++) acc[i][j][q] = 0.f;

        const int kbase = w * 192;
#pragma unroll
        for (int kt = 0; kt < 12; kt++) {
            int k0 = kbase + kt * 16;
            uint32_t a[2][4], b[2][2];
#pragma unroll
            for (int mi = 0; mi < 2; mi++) {
                int r0 = mi * 16 + g;
                a[mi][0] = *(const uint32_t*)&hsm[r0 * SH + k0 + 2 * tg];
                a[mi][1] = *(const uint32_t*)&hsm[(r0 + 8) * SH + k0 + 2 * tg];
                a[mi][2] = *(const uint32_t*)&hsm[r0 * SH + k0 + 2 * tg + 8];
                a[mi][3] = *(const uint32_t*)&hsm[(r0 + 8) * SH + k0 + 2 * tg + 8];
            }
#pragma unroll
            for (int ni = 0; ni < 2; ni++) {
                int r0 = ni * 8 + g;
                b[ni][0] = *(const uint32_t*)&wsm[r0 * SH + k0 + 2 * tg];
                b[ni][1] = *(const uint32_t*)&wsm[r0 * SH + k0 + 2 * tg + 8];
            }
#pragma unroll
            for (int mi = 0; mi < 2; mi++)
#pragma unroll
                for (int ni = 0; ni < 2; ni++)
                    mma16816(acc[mi][ni], a[mi], b[ni]);
        }

        // write warp partials
#pragma unroll
        for (int mi = 0; mi < 2; mi++)
#pragma unroll
            for (int ni = 0; ni < 2; ni++) {
                int r0 = mi * 16 + g;
                int c0 = ni * 8 + 2 * tg;
                *(float2*)&red[w * 512 + r0 * 16 + c0] =
                    make_float2(acc[mi][ni][0], acc[mi][ni][1]);
                *(float2*)&red[w * 512 + (r0 + 8) * 16 + c0] =
                    make_float2(acc[mi][ni][2], acc[mi][ni][3]);
            }
        __syncthreads();

        // reduce 8 warp partials, compute h, store h_next (fp16)
        const size_t base = (size_t)t * B_SZ * C_SZ;
        float hv[2];
        size_t idxs[2];
#pragma unroll
        for (int rep = 0; rep < 2; rep++) {
            int o = tid + rep * 256;
            float s = red[o];
#pragma unroll
            for (int q = 1; q < 8; q++) s += red[q * 512 + o];
            int b = o >> 4;
            int c = n0 + (o & 15);
            size_t idx = base + (size_t)b * C_SZ + c;
            float h = tanhf(g_pre[idx] + s);
            hnext[b * C_SZ + c] = __float2half_rn(h);
            hv[rep] = h;
            idxs[rep] = idx;
        }
        __syncthreads();                 // all h_next stores issued block-wide

        // barrier ARRIVE (release)
        if (tid == 0) {
            __threadfence();
            atomicAdd(&g_bar_ctr, 1u);
        }

        // epilogue overlapped with other blocks' arrival
#pragma unroll
        for (int rep = 0; rep < 2; rep++) {
            size_t idx = idxs[rep];
            float z = zc[idx];
            out_core[idx] = hv[rep] * (z * (1.0f / (1.0f + expf(-z))));
        }
        if (t == T_STEPS - 1) {
#pragma unroll
            for (int rep = 0; rep < 2; rep++) {
                int o = tid + rep * 256;
                int b = o >> 4;
                int c = n0 + (o & 15);
                h_core_f[b * C_SZ + c] = hv[rep];
            }
        }

        // barrier WAIT (acquire)
        if (tid == 0) {
            const unsigned target = (unsigned)(NBLK * (t + 1));
            unsigned v;
            do {
                asm volatile("ld.acquire.gpu.u32 %0, [%1];"
                             : "=r"(v) : "l"(&g_bar_ctr));
            } while (v < target);
        }
        __syncthreads();
    }
}

// ---------------- memory branch (independent scan, 4-deep prefetch) -------------
__global__ void k_mem(const float* __restrict__ xm, const float* __restrict__ zm,
                      const float* __restrict__ h0, const float* __restrict__ am,
                      float* __restrict__ out_mem, float* __restrict__ h_mem_f) {
    const int gid = blockIdx.x * blockDim.x + threadIdx.x;  // 0..49151
    const int m = gid & (M_SZ - 1);
    const float a = am[m];
    const float decay = 1.0f / (1.0f + expf(-a));
    float h = h0[gid];
    const size_t stride = (size_t)B_SZ * M_SZ;

    float xs[4], zs[4];
#pragma unroll
    for (int q = 0; q < 4; q++) {
        xs[q] = xm[gid + q * stride];
        zs[q] = zm[gid + q * stride];
    }
    size_t off = gid;
    for (int t0 = 0; t0 < T_STEPS; t0 += 4) {
        float xn[4], zn[4];
        if (t0 + 4 < T_STEPS) {
            size_t poff = off + 4 * stride;
#pragma unroll
            for (int q = 0; q < 4; q++) {
                xn[q] = xm[poff + q * stride];
                zn[q] = zm[poff + q * stride];
            }
        }
#pragma unroll
        for (int q = 0; q < 4; q++) {
            h = fmaf(decay, h, xs[q]);
            float z = zs[q];
            out_mem[off + q * stride] = h * (z * (1.0f / (1.0f + expf(-z))));
        }
#pragma unroll
        for (int q = 0; q < 4; q++) { xs[q] = xn[q]; zs[q] = zn[q]; }
        off += 4 * stride;
    }
    h_mem_f[gid] = h;
}

// ---------------- launch --------------------------------------------------------
extern "C" void kernel_launch(void* const* d_in, const int* in_sizes, int n_in,
                              void* d_out, int out_size) {
    const float* x_core  = (const float*)d_in[0];
    const float* z_core  = (const float*)d_in[1];
    const float* x_mem   = (const float*)d_in[2];
    const float* z_mem   = (const float*)d_in[3];
    const float* h0_core = (const float*)d_in[4];
    const float* h0_mem  = (const float*)d_in[5];
    const float* W_x     = (const float*)d_in[6];
    const float* W_h     = (const float*)d_in[7];
    const float* b_core  = (const float*)d_in[8];
    const float* a_mem   = (const float*)d_in[9];

    float* out       = (float*)d_out;
    float* out_core  = out;
    float* out_mem   = out + (size_t)T_STEPS * B_SZ * C_SZ;
    float* h_core_f  = out_mem + (size_t)T_STEPS * B_SZ * M_SZ;
    float* h_mem_f   = h_core_f + (size_t)B_SZ * C_SZ;

    cudaFuncSetAttribute(k_recurrent, cudaFuncAttributeMaxDynamicSharedMemorySize,
                         SMEM_STEP);

    // spectral norm of W_h -> g_scale
    k_gen_u<<<1, 512>>>();
    for (int it = 0; it < 3; it++) {
        k_mv_tn<<<96, 256>>>(W_h, 0);
        k_norm_v<<<1, 512>>>();
        k_mv_nt<<<48, 1024>>>(W_h);
        k_norm_u<<<1, 512>>>();
    }
    k_mv_tn<<<96, 256>>>(W_h, 1);   // g_t = u @ W
    k_sigma<<<1, 512>>>();

    // fp16 conversions (device globals referenced only in device code)
    k_scaleW16<<<(C_SZ * C_SZ / 2 + 255) / 256, 256>>>(W_h);
    k_convWx<<<(C_SZ * C_SZ / 2 + 255) / 256, 256>>>(W_x);
    k_convX<<<(N_ELEM_CORE / 2 + 255) / 256, 256>>>(x_core);
    k_init_h16<<<(B_SZ * C_SZ / 2 + 255) / 256, 256>>>(h0_core);

    // pre = x_core @ W_x^T + b_core (tensor cores)
    {
        dim3 grid(C_SZ / 64, (T_STEPS * B_SZ) / 64);  // (24, 128)
        k_gemm16<<<grid, 128>>>(b_core);
    }

    // memory branch (independent)
    k_mem<<<192, 256>>>(x_mem, z_mem, h0_mem, a_mem, out_mem, h_mem_f);

    // persistent recurrence over all 256 steps
    k_recurrent<<<NBLK, 256, SMEM_STEP>>>(z_core, out_core, h_core_f);
}